// round 2
// baseline (speedup 1.0000x reference)
#include <cuda_runtime.h>
#include <math.h>

#define NN 131072          // total nodes
#define EE 1048576         // total edges
#define BGRAPH 128         // graphs
#define NPG 1024           // nodes per graph
#define FULLMASK 0xffffffffu
#define RB 128             // rows (nodes) per block for warp-per-node kernels

// ---------------- scratch (device globals; no allocation allowed) ----------
__device__ int   g_cnt[NN];        // histogram, then CSR fill cursor
__device__ int   g_row[NN + 1];    // CSR row offsets (by dst)
__device__ int   g_esrc[EE];       // src node of each CSR-ordered edge
__device__ int   g_eid[EE];        // original edge id of each CSR-ordered edge
__device__ float g_e2n[NN * 32];   // segment_sum(edge_feat, dst)
__device__ float g_hA[NN * 32];    // ping
__device__ float g_hB[NN * 32];    // pong
__device__ float g_hop1[NN * 32];
__device__ float g_hop2[NN * 32];
__device__ float g_hop3[NN * 32];
__device__ float g_h3[NN];         // hop3 @ W3 (scalar per node)
__device__ float g_hop4[NN];       // sort channel (latent dim 96)

// ---------------- CSR build -------------------------------------------------
__global__ void k_zero() {
    int i = blockIdx.x * blockDim.x + threadIdx.x;
    if (i < NN) g_cnt[i] = 0;
}

__global__ void k_hist(const int* __restrict__ ei) {
    int e = blockIdx.x * blockDim.x + threadIdx.x;
    if (e < EE) atomicAdd(&g_cnt[ei[EE + e]], 1);
}

// single-block exclusive scan over NN counts; writes g_row and resets g_cnt
// to the same prefix (used as fill cursor).
__global__ void k_scan() {
    __shared__ int ss[1024];
    int t = threadIdx.x;
    int base = t * 128;
    int s = 0;
    for (int j = 0; j < 128; j++) s += g_cnt[base + j];
    ss[t] = s;
    __syncthreads();
    for (int off = 1; off < 1024; off <<= 1) {
        int v = ss[t];
        int a = (t >= off) ? ss[t - off] : 0;
        __syncthreads();
        ss[t] = v + a;
        __syncthreads();
    }
    int run = (t == 0) ? 0 : ss[t - 1];
    for (int j = 0; j < 128; j++) {
        int c = g_cnt[base + j];
        g_row[base + j] = run;
        g_cnt[base + j] = run;
        run += c;
    }
    if (t == 1023) g_row[NN] = run;   // == EE
}

__global__ void k_fill(const int* __restrict__ ei) {
    int e = blockIdx.x * blockDim.x + threadIdx.x;
    if (e < EE) {
        int dst = ei[EE + e];
        int pos = atomicAdd(&g_cnt[dst], 1);
        g_esrc[pos] = ei[e];
        g_eid[pos] = e;
    }
}

// ---------------- e2n: segment_sum(edge_feat, dst)  [N,32] -----------------
__global__ void k_e2n(const float* __restrict__ ef) {
    int w = threadIdx.x >> 5, lane = threadIdx.x & 31;
    int base = blockIdx.x * RB;
    for (int r = w; r < RB; r += 8) {
        int i = base + r;
        int b = g_row[i], e = g_row[i + 1];
        float acc = 0.f;
        int p = b;
        for (; p + 2 <= e; p += 2) {
            int e0 = g_eid[p], e1 = g_eid[p + 1];
            acc += ef[e0 * 32 + lane];
            acc += ef[e1 * 32 + lane];
        }
        if (p < e) acc += ef[g_eid[p] * 32 + lane];
        g_e2n[i * 32 + lane] = acc;
    }
}

// ---------------- h0 = node_feat @ W0[:128] + e2n @ W0[128:160] ------------
__global__ void k_gemm0(const float* __restrict__ nf, const float* __restrict__ W0) {
    __shared__ float Ws[160 * 32];
    int t = threadIdx.x;
    for (int i = t; i < 160 * 32; i += 256) Ws[i] = W0[i];
    __syncthreads();
    int w = t >> 5, lane = t & 31;
    int base = blockIdx.x * 128;
    for (int r = w; r < 128; r += 8) {
        int i = base + r;
        float xr[5];
#pragma unroll
        for (int j = 0; j < 4; j++) xr[j] = nf[i * 128 + j * 32 + lane];
        xr[4] = g_e2n[i * 32 + lane];
        float acc = 0.f;
#pragma unroll
        for (int k = 0; k < 160; k++) {
            float v = __shfl_sync(FULLMASK, xr[k >> 5], k & 31);
            acc += v * Ws[k * 32 + lane];
        }
        g_hA[i * 32 + lane] = acc;
    }
}

// ---------------- fused aggregate + tanh + next-layer GEMM -----------------
// L=0: hin=g_hA, hop=g_hop1, hout=g_hB (z @ W1)
// L=1: hin=g_hB, hop=g_hop2, hout=g_hA (z @ W2)
// L=2: hin=g_hA, hop=g_hop3, hout=g_h3 (z @ W3, 32->1)
template <int L>
__global__ void k_agg(const float* __restrict__ bias, const float* __restrict__ W) {
    constexpr bool LAST = (L == 2);
    const float* __restrict__ hin = (L == 1) ? g_hB : g_hA;
    float* __restrict__ hop = (L == 0) ? g_hop1 : (L == 1) ? g_hop2 : g_hop3;

    __shared__ float Ws[32 * 32];
    int t = threadIdx.x;
    if (!LAST) {
        for (int i = t; i < 1024; i += 256) Ws[i] = W[i];
        __syncthreads();
    }
    int w = t >> 5, lane = t & 31;
    float bl = bias[lane];
    float wl = LAST ? W[lane] : 0.f;
    int base = blockIdx.x * RB;
    for (int r = w; r < RB; r += 8) {
        int i = base + r;
        int b0 = g_row[i], e0 = g_row[i + 1];
        float z = hin[i * 32 + lane];
        int p = b0;
        for (; p + 2 <= e0; p += 2) {
            int s0 = g_esrc[p], s1 = g_esrc[p + 1];
            z += hin[s0 * 32 + lane];
            z += hin[s1 * 32 + lane];
        }
        if (p < e0) z += hin[g_esrc[p] * 32 + lane];
        z = tanhf((z + bl) / (float)(e0 - b0 + 1));
        hop[i * 32 + lane] = z;
        if (!LAST) {
            float* __restrict__ hout = (L == 0) ? g_hB : g_hA;
            float o = 0.f;
#pragma unroll
            for (int k = 0; k < 32; k++)
                o += __shfl_sync(FULLMASK, z, k) * Ws[k * 32 + lane];
            hout[i * 32 + lane] = o;
        } else {
            float o = z * wl;
#pragma unroll
            for (int off = 16; off; off >>= 1) o += __shfl_down_sync(FULLMASK, o, off);
            if (lane == 0) g_h3[i] = o;
        }
    }
}

// ---------------- 1-dim aggregate for last hop -----------------------------
__global__ void k_agg1d(const float* __restrict__ bias) {
    int i = blockIdx.x * blockDim.x + threadIdx.x;
    if (i >= NN) return;
    int b = g_row[i], e = g_row[i + 1];
    float z = g_h3[i];
    for (int p = b; p < e; p++) z += g_h3[g_esrc[p]];
    g_hop4[i] = tanhf((z + bias[0]) / (float)(e - b + 1));
}

// ---------------- per-graph: sort-pool + conv1 + pool + conv2 + dense ------
__global__ void k_final(const float* __restrict__ w1, const float* __restrict__ b1,
                        const float* __restrict__ w2, const float* __restrict__ b2,
                        const float* __restrict__ wo, const float* __restrict__ bo,
                        float* __restrict__ out) {
    __shared__ float sv[1024];
    __shared__ int   si[1024];
    __shared__ float sfeat[30 * 97];
    __shared__ float sw1[16 * 97];
    __shared__ float sc1[16 * 30];
    __shared__ float sp2[16 * 15];
    __shared__ float sw2[32 * 16 * 5];
    __shared__ float sc2[352];

    int t = threadIdx.x, g = blockIdx.x;
    sv[t] = g_hop4[g * NPG + t];
    si[t] = t;
    __syncthreads();

    // full bitonic sort, descending by value, ties -> lower index first
    for (int k = 2; k <= 1024; k <<= 1) {
        for (int j = k >> 1; j > 0; j >>= 1) {
            int ixj = t ^ j;
            if (ixj > t) {
                float v1 = sv[t], v2 = sv[ixj];
                int i1 = si[t], i2 = si[ixj];
                bool before = (v1 > v2) || (v1 == v2 && i1 < i2);
                bool asc = ((t & k) == 0);
                if (asc != before) {
                    sv[t] = v2; sv[ixj] = v1;
                    si[t] = i2; si[ixj] = i1;
                }
            }
            __syncthreads();
        }
    }

    // stage weights + gather top-30 feature rows
    for (int i = t; i < 16 * 97; i += 1024) sw1[i] = w1[i];
    for (int i = t; i < 32 * 16 * 5; i += 1024) sw2[i] = w2[i];
    for (int i = t; i < 30 * 97; i += 1024) {
        int kk = i / 97, d = i % 97;
        int n = g * NPG + si[kk];
        float f;
        if (d < 32)      f = g_hop1[n * 32 + d];
        else if (d < 64) f = g_hop2[n * 32 + (d - 32)];
        else if (d < 96) f = g_hop3[n * 32 + (d - 64)];
        else             f = g_hop4[n];
        sfeat[i] = f;
    }
    __syncthreads();

    // conv1: 1->16 channels, kernel 97, stride 97 -> [16, 30], relu
    if (t < 480) {
        int c1 = t / 30, kk = t % 30;
        float acc = b1[c1];
        for (int d = 0; d < 97; d++) acc += sw1[c1 * 97 + d] * sfeat[kk * 97 + d];
        sc1[c1 * 30 + kk] = fmaxf(acc, 0.f);
    }
    __syncthreads();

    // maxpool(2,2) -> [16, 15]
    if (t < 240) {
        int c1 = t / 15, j = t % 15;
        sp2[c1 * 15 + j] = fmaxf(sc1[c1 * 30 + 2 * j], sc1[c1 * 30 + 2 * j + 1]);
    }
    __syncthreads();

    // conv2: 16->32 channels, kernel 5 -> [32, 11], relu
    if (t < 352) {
        int c2 = t / 11, tt = t % 11;
        float acc = b2[c2];
        for (int c1 = 0; c1 < 16; c1++) {
#pragma unroll
            for (int kk = 0; kk < 5; kk++)
                acc += sw2[(c2 * 16 + c1) * 5 + kk] * sp2[c1 * 15 + tt + kk];
        }
        sc2[c2 * 11 + tt] = fmaxf(acc, 0.f);
    }
    __syncthreads();

    // dense [352] @ [352,2] + relu
    if (t < 2) {
        float acc = bo[t];
        for (int f = 0; f < 352; f++) acc += sc2[f] * wo[f * 2 + t];
        out[g * 2 + t] = fmaxf(acc, 0.f);
    }
}

// ---------------- launch ----------------------------------------------------
extern "C" void kernel_launch(void* const* d_in, const int* in_sizes, int n_in,
                              void* d_out, int out_size) {
    (void)in_sizes; (void)n_in; (void)out_size;
    const float* node_feat = (const float*)d_in[0];
    const float* edge_feat = (const float*)d_in[1];
    const int*   ei        = (const int*)d_in[2];
    const float* W0 = (const float*)d_in[3];  const float* b0 = (const float*)d_in[4];
    const float* W1 = (const float*)d_in[5];  const float* b1 = (const float*)d_in[6];
    const float* W2 = (const float*)d_in[7];  const float* b2 = (const float*)d_in[8];
    const float* W3 = (const float*)d_in[9];  const float* b3 = (const float*)d_in[10];
    const float* wc1 = (const float*)d_in[11]; const float* bc1 = (const float*)d_in[12];
    const float* wc2 = (const float*)d_in[13]; const float* bc2 = (const float*)d_in[14];
    const float* wo  = (const float*)d_in[15]; const float* bo  = (const float*)d_in[16];
    float* out = (float*)d_out;

    k_zero<<<NN / 256, 256>>>();
    k_hist<<<EE / 256, 256>>>(ei);
    k_scan<<<1, 1024>>>();
    k_fill<<<EE / 256, 256>>>(ei);
    k_e2n<<<NN / RB, 256>>>(edge_feat);
    k_gemm0<<<NN / 128, 256>>>(node_feat, W0);
    k_agg<0><<<NN / RB, 256>>>(b0, W1);
    k_agg<1><<<NN / RB, 256>>>(b1, W2);
    k_agg<2><<<NN / RB, 256>>>(b2, W3);
    k_agg1d<<<NN / 256, 256>>>(b3);
    k_final<<<BGRAPH, 1024>>>(wc1, bc1, wc2, bc2, wo, bo, out);
}

// round 3
// speedup vs baseline: 1.9985x; 1.9985x over previous
#include <cuda_runtime.h>
#include <math.h>

#define NN 131072          // total nodes
#define EE 1048576         // total edges
#define BGRAPH 128         // graphs
#define NPG 1024           // nodes per graph
#define FULLMASK 0xffffffffu

// ---------------- scratch (device globals; no allocation allowed) ----------
__device__ int    g_cnt[NN];         // histogram, then CSR fill cursor
__device__ int    g_row[NN + 1];     // CSR row offsets (by dst)
__device__ int2   g_edge[EE];        // (src, eid) per CSR-ordered edge
__device__ float4 g_hA[NN * 8];      // ping  (32 ch per node as 8 float4)
__device__ float4 g_hB[NN * 8];      // pong
__device__ float4 g_hop1[NN * 8];
__device__ float4 g_hop2[NN * 8];
__device__ float4 g_hop3[NN * 8];
__device__ float  g_h3[NN];          // hop3 @ W3 (scalar per node)
__device__ float  g_hop4[NN];        // sort channel (latent dim 96)

__device__ __forceinline__ void add4(float4& a, const float4 b) {
    a.x += b.x; a.y += b.y; a.z += b.z; a.w += b.w;
}

// ---------------- CSR build -------------------------------------------------
__global__ void k_zero() {
    int i = blockIdx.x * blockDim.x + threadIdx.x;
    if (i < NN) g_cnt[i] = 0;
}

__global__ void k_hist(const int* __restrict__ ei) {
    int e = (blockIdx.x * blockDim.x + threadIdx.x) * 4;
    int4 d = *reinterpret_cast<const int4*>(ei + EE + e);
    atomicAdd(&g_cnt[d.x], 1);
    atomicAdd(&g_cnt[d.y], 1);
    atomicAdd(&g_cnt[d.z], 1);
    atomicAdd(&g_cnt[d.w], 1);
}

// single-block exclusive scan over NN counts; writes g_row and resets g_cnt
// to the same prefix (used as fill cursor).
__global__ void k_scan() {
    __shared__ int ss[1024];
    int t = threadIdx.x;
    int4* c4 = reinterpret_cast<int4*>(g_cnt);
    int4* r4 = reinterpret_cast<int4*>(g_row);
    int s = 0;
#pragma unroll 8
    for (int j = 0; j < 32; j++) {
        int4 c = c4[t * 32 + j];
        s += c.x + c.y + c.z + c.w;
    }
    ss[t] = s;
    __syncthreads();
    for (int off = 1; off < 1024; off <<= 1) {
        int v = ss[t];
        int a = (t >= off) ? ss[t - off] : 0;
        __syncthreads();
        ss[t] = v + a;
        __syncthreads();
    }
    int run = (t == 0) ? 0 : ss[t - 1];
#pragma unroll 8
    for (int j = 0; j < 32; j++) {
        int4 c = c4[t * 32 + j];
        int4 r;
        r.x = run;
        r.y = r.x + c.x;
        r.z = r.y + c.y;
        r.w = r.z + c.z;
        run = r.w + c.w;
        r4[t * 32 + j] = r;
        c4[t * 32 + j] = r;
    }
    if (t == 1023) g_row[NN] = run;   // == EE
}

__global__ void k_fill(const int* __restrict__ ei) {
    int e = (blockIdx.x * blockDim.x + threadIdx.x) * 2;
    int2 srcs = *reinterpret_cast<const int2*>(ei + e);
    int2 dsts = *reinterpret_cast<const int2*>(ei + EE + e);
    int p0 = atomicAdd(&g_cnt[dsts.x], 1);
    g_edge[p0] = make_int2(srcs.x, e);
    int p1 = atomicAdd(&g_cnt[dsts.y], 1);
    g_edge[p1] = make_int2(srcs.y, e + 1);
}

// ---------------- fused e2n + h0 = [node_feat, e2n] @ W0 -------------------
// warp = 4 groups of 8 lanes; group handles one row; lane s holds 4 channels.
__global__ void k_gemm0(const float* __restrict__ nf, const float* __restrict__ ef,
                        const float* __restrict__ W0) {
    __shared__ float4 Ws[160 * 8];    // 20 KB
    int t = threadIdx.x;
    const float4* W04 = reinterpret_cast<const float4*>(W0);
    for (int i = t; i < 160 * 8; i += 256) Ws[i] = W04[i];
    __syncthreads();
    int w = t >> 5, lane = t & 31;
    int g = lane >> 3, s = lane & 7;
    const float4* nf4 = reinterpret_cast<const float4*>(nf);
    const float4* ef4 = reinterpret_cast<const float4*>(ef);
    int base = blockIdx.x * 128;

    for (int r = w * 4 + g; r < 128; r += 32) {
        int row = base + r;
        int b = g_row[row], e = g_row[row + 1];
        // e2n aggregation for this row (chunk 32+s of the 160-vector)
        float4 acc = make_float4(0.f, 0.f, 0.f, 0.f);
        int p = b;
        for (; p + 2 <= e; p += 2) {
            int e0 = g_edge[p].y, e1 = g_edge[p + 1].y;
            float4 a0 = ef4[e0 * 8 + s];
            float4 a1 = ef4[e1 * 8 + s];
            add4(acc, a0); add4(acc, a1);
        }
        if (p < e) { float4 a0 = ef4[g_edge[p].y * 8 + s]; add4(acc, a0); }

        // lane s holds chunks s, s+8, s+16, s+24 (nf) and s+32 (e2n)
        float4 xr[5];
#pragma unroll
        for (int j = 0; j < 4; j++) xr[j] = nf4[row * 32 + s + 8 * j];
        xr[4] = acc;

        float4 o = make_float4(0.f, 0.f, 0.f, 0.f);
#pragma unroll
        for (int j = 0; j < 5; j++) {
#pragma unroll
            for (int kk = 0; kk < 32; kk++) {
                int k = j * 32 + kk;
                float c;
                switch (kk & 3) {
                    case 0: c = xr[j].x; break;
                    case 1: c = xr[j].y; break;
                    case 2: c = xr[j].z; break;
                    default: c = xr[j].w; break;
                }
                float xk = __shfl_sync(FULLMASK, c, (lane & 24) | ((kk >> 2) & 7));
                float4 wv = Ws[k * 8 + s];
                o.x += xk * wv.x; o.y += xk * wv.y;
                o.z += xk * wv.z; o.w += xk * wv.w;
            }
        }
        g_hA[row * 8 + s] = o;
    }
}

// ---------------- fused aggregate + tanh + next-layer GEMM -----------------
// L=0: hin=g_hA, hop=g_hop1, hout=g_hB (z @ W1)
// L=1: hin=g_hB, hop=g_hop2, hout=g_hA (z @ W2)
// L=2: hin=g_hA, hop=g_hop3, hout=g_h3 (z @ W3, 32->1)
template <int L>
__global__ void k_agg(const float* __restrict__ bias, const float* __restrict__ W) {
    constexpr bool LAST = (L == 2);
    const float4* __restrict__ hin = (L == 1) ? g_hB : g_hA;
    float4* __restrict__ hop = (L == 0) ? g_hop1 : (L == 1) ? g_hop2 : g_hop3;

    __shared__ float4 Ws[32 * 8];
    int t = threadIdx.x;
    if (!LAST) {
        const float4* W4 = reinterpret_cast<const float4*>(W);
        for (int i = t; i < 32 * 8; i += 256) Ws[i] = W4[i];
        __syncthreads();
    }
    int w = t >> 5, lane = t & 31;
    int g = lane >> 3, s = lane & 7;
    float4 b4 = reinterpret_cast<const float4*>(bias)[s];
    float4 w3 = LAST ? reinterpret_cast<const float4*>(W)[s]
                     : make_float4(0.f, 0.f, 0.f, 0.f);
    int base = blockIdx.x * 128;

    for (int r = w * 4 + g; r < 128; r += 32) {
        int row = base + r;
        int b0 = g_row[row], e0 = g_row[row + 1];
        float4 z = hin[row * 8 + s];
        int p = b0;
        for (; p + 2 <= e0; p += 2) {
            int s0 = g_edge[p].x, s1 = g_edge[p + 1].x;
            float4 a0 = hin[s0 * 8 + s];
            float4 a1 = hin[s1 * 8 + s];
            add4(z, a0); add4(z, a1);
        }
        if (p < e0) { float4 a0 = hin[g_edge[p].x * 8 + s]; add4(z, a0); }

        float inv = 1.f / (float)(e0 - b0 + 1);
        z.x = tanhf((z.x + b4.x) * inv);
        z.y = tanhf((z.y + b4.y) * inv);
        z.z = tanhf((z.z + b4.z) * inv);
        z.w = tanhf((z.w + b4.w) * inv);
        hop[row * 8 + s] = z;

        if (!LAST) {
            float4* __restrict__ hout = (L == 0) ? g_hB : g_hA;
            float4 o = make_float4(0.f, 0.f, 0.f, 0.f);
#pragma unroll
            for (int k = 0; k < 32; k++) {
                float c;
                switch (k & 3) {
                    case 0: c = z.x; break;
                    case 1: c = z.y; break;
                    case 2: c = z.z; break;
                    default: c = z.w; break;
                }
                float zk = __shfl_sync(FULLMASK, c, (lane & 24) | (k >> 2));
                float4 wv = Ws[k * 8 + s];
                o.x += zk * wv.x; o.y += zk * wv.y;
                o.z += zk * wv.z; o.w += zk * wv.w;
            }
            hout[row * 8 + s] = o;
        } else {
            float o = z.x * w3.x + z.y * w3.y + z.z * w3.z + z.w * w3.w;
            o += __shfl_down_sync(FULLMASK, o, 4);
            o += __shfl_down_sync(FULLMASK, o, 2);
            o += __shfl_down_sync(FULLMASK, o, 1);
            if (s == 0) g_h3[row] = o;
        }
    }
}

// ---------------- 1-dim aggregate for last hop -----------------------------
__global__ void k_agg1d(const float* __restrict__ bias) {
    int i = blockIdx.x * blockDim.x + threadIdx.x;
    if (i >= NN) return;
    int b = g_row[i], e = g_row[i + 1];
    float z = g_h3[i];
    int p = b;
    for (; p + 4 <= e; p += 4) {
        float a0 = g_h3[g_edge[p].x];
        float a1 = g_h3[g_edge[p + 1].x];
        float a2 = g_h3[g_edge[p + 2].x];
        float a3 = g_h3[g_edge[p + 3].x];
        z += (a0 + a1) + (a2 + a3);
    }
    for (; p < e; p++) z += g_h3[g_edge[p].x];
    g_hop4[i] = tanhf((z + bias[0]) / (float)(e - b + 1));
}

// ---------------- per-graph: sort-pool + conv1 + pool + conv2 + dense ------
__global__ void k_final(const float* __restrict__ w1, const float* __restrict__ b1,
                        const float* __restrict__ w2, const float* __restrict__ b2,
                        const float* __restrict__ wo, const float* __restrict__ bo,
                        float* __restrict__ out) {
    __shared__ float sv[1024];
    __shared__ int   si[1024];
    __shared__ float sfeat[30 * 97];
    __shared__ float sw1[16 * 97];
    __shared__ float sc1[16 * 30];
    __shared__ float sp2[16 * 15];
    __shared__ float sw2[32 * 16 * 5];
    __shared__ float sc2[352];

    int t = threadIdx.x, g = blockIdx.x;
    sv[t] = g_hop4[g * NPG + t];
    si[t] = t;
    __syncthreads();

    // full bitonic sort, descending by value, ties -> lower index first
    for (int k = 2; k <= 1024; k <<= 1) {
        for (int j = k >> 1; j > 0; j >>= 1) {
            int ixj = t ^ j;
            if (ixj > t) {
                float v1 = sv[t], v2 = sv[ixj];
                int i1 = si[t], i2 = si[ixj];
                bool before = (v1 > v2) || (v1 == v2 && i1 < i2);
                bool asc = ((t & k) == 0);
                if (asc != before) {
                    sv[t] = v2; sv[ixj] = v1;
                    si[t] = i2; si[ixj] = i1;
                }
            }
            __syncthreads();
        }
    }

    const float* h1 = reinterpret_cast<const float*>(g_hop1);
    const float* h2 = reinterpret_cast<const float*>(g_hop2);
    const float* h3 = reinterpret_cast<const float*>(g_hop3);

    // stage weights + gather top-30 feature rows
    for (int i = t; i < 16 * 97; i += 1024) sw1[i] = w1[i];
    for (int i = t; i < 32 * 16 * 5; i += 1024) sw2[i] = w2[i];
    for (int i = t; i < 30 * 97; i += 1024) {
        int kk = i / 97, d = i % 97;
        int n = g * NPG + si[kk];
        float f;
        if (d < 32)      f = h1[n * 32 + d];
        else if (d < 64) f = h2[n * 32 + (d - 32)];
        else if (d < 96) f = h3[n * 32 + (d - 64)];
        else             f = g_hop4[n];
        sfeat[i] = f;
    }
    __syncthreads();

    // conv1: 1->16 channels, kernel 97, stride 97 -> [16, 30], relu
    if (t < 480) {
        int c1 = t / 30, kk = t % 30;
        float acc = b1[c1];
        for (int d = 0; d < 97; d++) acc += sw1[c1 * 97 + d] * sfeat[kk * 97 + d];
        sc1[c1 * 30 + kk] = fmaxf(acc, 0.f);
    }
    __syncthreads();

    // maxpool(2,2) -> [16, 15]
    if (t < 240) {
        int c1 = t / 15, j = t % 15;
        sp2[c1 * 15 + j] = fmaxf(sc1[c1 * 30 + 2 * j], sc1[c1 * 30 + 2 * j + 1]);
    }
    __syncthreads();

    // conv2: 16->32 channels, kernel 5 -> [32, 11], relu
    if (t < 352) {
        int c2 = t / 11, tt = t % 11;
        float acc = b2[c2];
        for (int c1 = 0; c1 < 16; c1++) {
#pragma unroll
            for (int kk = 0; kk < 5; kk++)
                acc += sw2[(c2 * 16 + c1) * 5 + kk] * sp2[c1 * 15 + tt + kk];
        }
        sc2[c2 * 11 + tt] = fmaxf(acc, 0.f);
    }
    __syncthreads();

    // dense [352] @ [352,2] + relu
    if (t < 2) {
        float acc = bo[t];
        for (int f = 0; f < 352; f++) acc += sc2[f] * wo[f * 2 + t];
        out[g * 2 + t] = fmaxf(acc, 0.f);
    }
}

// ---------------- launch ----------------------------------------------------
extern "C" void kernel_launch(void* const* d_in, const int* in_sizes, int n_in,
                              void* d_out, int out_size) {
    (void)in_sizes; (void)n_in; (void)out_size;
    const float* node_feat = (const float*)d_in[0];
    const float* edge_feat = (const float*)d_in[1];
    const int*   ei        = (const int*)d_in[2];
    const float* W0 = (const float*)d_in[3];  const float* b0 = (const float*)d_in[4];
    const float* W1 = (const float*)d_in[5];  const float* b1 = (const float*)d_in[6];
    const float* W2 = (const float*)d_in[7];  const float* b2 = (const float*)d_in[8];
    const float* W3 = (const float*)d_in[9];  const float* b3 = (const float*)d_in[10];
    const float* wc1 = (const float*)d_in[11]; const float* bc1 = (const float*)d_in[12];
    const float* wc2 = (const float*)d_in[13]; const float* bc2 = (const float*)d_in[14];
    const float* wo  = (const float*)d_in[15]; const float* bo  = (const float*)d_in[16];
    float* out = (float*)d_out;

    k_zero<<<NN / 256, 256>>>();
    k_hist<<<EE / 1024, 256>>>(ei);
    k_scan<<<1, 1024>>>();
    k_fill<<<EE / 512, 256>>>(ei);
    k_gemm0<<<NN / 128, 256>>>(node_feat, edge_feat, W0);
    k_agg<0><<<NN / 128, 256>>>(b0, W1);
    k_agg<1><<<NN / 128, 256>>>(b1, W2);
    k_agg<2><<<NN / 128, 256>>>(b2, W3);
    k_agg1d<<<NN / 256, 256>>>(b3);
    k_final<<<BGRAPH, 1024>>>(wc1, bc1, wc2, bc2, wo, bo, out);
}

// round 4
// speedup vs baseline: 2.5456x; 1.2737x over previous
#include <cuda_runtime.h>
#include <math.h>

#define NN 131072          // total nodes
#define EE 1048576         // total edges
#define BGRAPH 128         // graphs
#define NPG 1024           // nodes per graph
#define FULLMASK 0xffffffffu

// ---------------- scratch (device globals; no allocation allowed) ----------
__device__ int    g_cnt[NN];         // histogram, then CSR fill cursor
__device__ int    g_row[NN + 1];     // CSR row offsets (by dst)
__device__ int    g_bsum[128];       // per-block partial sums for scan
__device__ int2   g_edge[EE];        // (src, eid) per CSR-ordered edge
__device__ float4 g_hA[NN * 8];      // ping  (32 ch per node as 8 float4)
__device__ float4 g_hB[NN * 8];      // pong
__device__ float4 g_hop1[NN * 8];
__device__ float4 g_hop2[NN * 8];
__device__ float4 g_hop3[NN * 8];
__device__ float  g_h3[NN];          // hop3 @ W3 (scalar per node)
__device__ float  g_hop4[NN];        // sort channel (latent dim 96)

__device__ __forceinline__ void add4(float4& a, const float4 b) {
    a.x += b.x; a.y += b.y; a.z += b.z; a.w += b.w;
}

// ---------------- CSR build -------------------------------------------------
__global__ void k_zero() {
    int i = blockIdx.x * blockDim.x + threadIdx.x;
    if (i < NN) g_cnt[i] = 0;
}

__global__ void k_hist(const int* __restrict__ ei) {
    int e = (blockIdx.x * blockDim.x + threadIdx.x) * 8;
    int4 d0 = *reinterpret_cast<const int4*>(ei + EE + e);
    int4 d1 = *reinterpret_cast<const int4*>(ei + EE + e + 4);
    atomicAdd(&g_cnt[d0.x], 1);
    atomicAdd(&g_cnt[d0.y], 1);
    atomicAdd(&g_cnt[d0.z], 1);
    atomicAdd(&g_cnt[d0.w], 1);
    atomicAdd(&g_cnt[d1.x], 1);
    atomicAdd(&g_cnt[d1.y], 1);
    atomicAdd(&g_cnt[d1.z], 1);
    atomicAdd(&g_cnt[d1.w], 1);
}

// 3-phase parallel exclusive scan of g_cnt -> g_row (and g_cnt = cursor copy)
// phase A: 128 blocks x 256 threads, thread = one int4 (block covers 1024 ints)
__global__ void k_scanA() {
    __shared__ int ws[8];
    int t = threadIdx.x;
    int i = blockIdx.x * 256 + t;
    int lane = t & 31, wid = t >> 5;
    int4 c = reinterpret_cast<const int4*>(g_cnt)[i];
    int s = c.x + c.y + c.z + c.w;
    int v = s;
#pragma unroll
    for (int o = 1; o < 32; o <<= 1) {
        int n = __shfl_up_sync(FULLMASK, v, o);
        if (lane >= o) v += n;
    }
    if (lane == 31) ws[wid] = v;
    __syncthreads();
    if (wid == 0) {
        int bv = (lane < 8) ? ws[lane] : 0;
#pragma unroll
        for (int o = 1; o < 8; o <<= 1) {
            int n = __shfl_up_sync(FULLMASK, bv, o);
            if (lane >= o) bv += n;
        }
        if (lane < 8) ws[lane] = bv;
    }
    __syncthreads();
    int excl = v - s + (wid ? ws[wid - 1] : 0);
    int4 r;
    r.x = excl;
    r.y = r.x + c.x;
    r.z = r.y + c.y;
    r.w = r.z + c.z;
    reinterpret_cast<int4*>(g_row)[i] = r;
    if (t == 255) g_bsum[blockIdx.x] = excl + s;   // block total offset base
}

// phase B: exclusive scan of the 128 block sums (1 block, 128 threads)
__global__ void k_scanB() {
    __shared__ int ws[4];
    int t = threadIdx.x;
    int lane = t & 31, wid = t >> 5;
    int s = g_bsum[t];
    int v = s;
#pragma unroll
    for (int o = 1; o < 32; o <<= 1) {
        int n = __shfl_up_sync(FULLMASK, v, o);
        if (lane >= o) v += n;
    }
    if (lane == 31) ws[wid] = v;
    __syncthreads();
    int off = 0;
    for (int j = 0; j < wid; j++) off += ws[j];
    g_bsum[t] = v - s + off;
}

// phase C: add block offsets; copy to g_cnt (fill cursor); set sentinel
__global__ void k_scanC() {
    int t = threadIdx.x;
    int i = blockIdx.x * 256 + t;
    int off = g_bsum[blockIdx.x];
    int4 r = reinterpret_cast<const int4*>(g_row)[i];
    r.x += off; r.y += off; r.z += off; r.w += off;
    reinterpret_cast<int4*>(g_row)[i] = r;
    reinterpret_cast<int4*>(g_cnt)[i] = r;
    if (i == 0) g_row[NN] = EE;
}

__global__ void k_fill(const int* __restrict__ ei) {
    int e = (blockIdx.x * blockDim.x + threadIdx.x) * 4;
    int4 srcs = *reinterpret_cast<const int4*>(ei + e);
    int4 dsts = *reinterpret_cast<const int4*>(ei + EE + e);
    int p0 = atomicAdd(&g_cnt[dsts.x], 1);
    int p1 = atomicAdd(&g_cnt[dsts.y], 1);
    int p2 = atomicAdd(&g_cnt[dsts.z], 1);
    int p3 = atomicAdd(&g_cnt[dsts.w], 1);
    g_edge[p0] = make_int2(srcs.x, e);
    g_edge[p1] = make_int2(srcs.y, e + 1);
    g_edge[p2] = make_int2(srcs.z, e + 2);
    g_edge[p3] = make_int2(srcs.w, e + 3);
}

// ---------------- fused e2n + h0 = [node_feat, e2n] @ W0 -------------------
// warp = 4 groups of 8 lanes; group handles one row; lane s holds 4 channels.
__global__ void k_gemm0(const float* __restrict__ nf, const float* __restrict__ ef,
                        const float* __restrict__ W0) {
    __shared__ float4 Ws[160 * 8];    // 20 KB
    int t = threadIdx.x;
    const float4* W04 = reinterpret_cast<const float4*>(W0);
    for (int i = t; i < 160 * 8; i += 256) Ws[i] = W04[i];
    __syncthreads();
    int w = t >> 5, lane = t & 31;
    int g = lane >> 3, s = lane & 7;
    const float4* nf4 = reinterpret_cast<const float4*>(nf);
    const float4* ef4 = reinterpret_cast<const float4*>(ef);
    int base = blockIdx.x * 128;

    for (int r = w * 4 + g; r < 128; r += 32) {
        int row = base + r;
        int b = g_row[row], e = g_row[row + 1];
        float4 acc = make_float4(0.f, 0.f, 0.f, 0.f);
        int p = b;
        for (; p + 4 <= e; p += 4) {
            int e0 = g_edge[p].y, e1 = g_edge[p + 1].y;
            int e2 = g_edge[p + 2].y, e3 = g_edge[p + 3].y;
            float4 a0 = ef4[e0 * 8 + s];
            float4 a1 = ef4[e1 * 8 + s];
            float4 a2 = ef4[e2 * 8 + s];
            float4 a3 = ef4[e3 * 8 + s];
            add4(acc, a0); add4(acc, a1); add4(acc, a2); add4(acc, a3);
        }
        for (; p < e; p++) { float4 a0 = ef4[g_edge[p].y * 8 + s]; add4(acc, a0); }

        // lane s holds chunks s, s+8, s+16, s+24 (nf) and s+32 (e2n)
        float4 xr[5];
#pragma unroll
        for (int j = 0; j < 4; j++) xr[j] = nf4[row * 32 + s + 8 * j];
        xr[4] = acc;

        float4 o = make_float4(0.f, 0.f, 0.f, 0.f);
#pragma unroll
        for (int j = 0; j < 5; j++) {
#pragma unroll
            for (int kk = 0; kk < 32; kk++) {
                int k = j * 32 + kk;
                float c;
                switch (kk & 3) {
                    case 0: c = xr[j].x; break;
                    case 1: c = xr[j].y; break;
                    case 2: c = xr[j].z; break;
                    default: c = xr[j].w; break;
                }
                float xk = __shfl_sync(FULLMASK, c, (lane & 24) | ((kk >> 2) & 7));
                float4 wv = Ws[k * 8 + s];
                o.x += xk * wv.x; o.y += xk * wv.y;
                o.z += xk * wv.z; o.w += xk * wv.w;
            }
        }
        g_hA[row * 8 + s] = o;
    }
}

// ---------------- fused aggregate + tanh + next-layer GEMM -----------------
template <int L>
__global__ void k_agg(const float* __restrict__ bias, const float* __restrict__ W) {
    constexpr bool LAST = (L == 2);
    const float4* __restrict__ hin = (L == 1) ? g_hB : g_hA;
    float4* __restrict__ hop = (L == 0) ? g_hop1 : (L == 1) ? g_hop2 : g_hop3;

    __shared__ float4 Ws[32 * 8];
    int t = threadIdx.x;
    if (!LAST) {
        const float4* W4 = reinterpret_cast<const float4*>(W);
        for (int i = t; i < 32 * 8; i += 256) Ws[i] = W4[i];
        __syncthreads();
    }
    int w = t >> 5, lane = t & 31;
    int g = lane >> 3, s = lane & 7;
    float4 b4 = reinterpret_cast<const float4*>(bias)[s];
    float4 w3 = LAST ? reinterpret_cast<const float4*>(W)[s]
                     : make_float4(0.f, 0.f, 0.f, 0.f);
    int base = blockIdx.x * 128;

    for (int r = w * 4 + g; r < 128; r += 32) {
        int row = base + r;
        int b0 = g_row[row], e0 = g_row[row + 1];
        float4 z = hin[row * 8 + s];
        int p = b0;
        for (; p + 4 <= e0; p += 4) {
            int s0 = g_edge[p].x, s1 = g_edge[p + 1].x;
            int s2 = g_edge[p + 2].x, s3 = g_edge[p + 3].x;
            float4 a0 = hin[s0 * 8 + s];
            float4 a1 = hin[s1 * 8 + s];
            float4 a2 = hin[s2 * 8 + s];
            float4 a3 = hin[s3 * 8 + s];
            add4(z, a0); add4(z, a1); add4(z, a2); add4(z, a3);
        }
        for (; p < e0; p++) { float4 a0 = hin[g_edge[p].x * 8 + s]; add4(z, a0); }

        float inv = 1.f / (float)(e0 - b0 + 1);
        z.x = tanhf((z.x + b4.x) * inv);
        z.y = tanhf((z.y + b4.y) * inv);
        z.z = tanhf((z.z + b4.z) * inv);
        z.w = tanhf((z.w + b4.w) * inv);
        hop[row * 8 + s] = z;

        if (!LAST) {
            float4* __restrict__ hout = (L == 0) ? g_hB : g_hA;
            float4 o = make_float4(0.f, 0.f, 0.f, 0.f);
#pragma unroll
            for (int k = 0; k < 32; k++) {
                float c;
                switch (k & 3) {
                    case 0: c = z.x; break;
                    case 1: c = z.y; break;
                    case 2: c = z.z; break;
                    default: c = z.w; break;
                }
                float zk = __shfl_sync(FULLMASK, c, (lane & 24) | (k >> 2));
                float4 wv = Ws[k * 8 + s];
                o.x += zk * wv.x; o.y += zk * wv.y;
                o.z += zk * wv.z; o.w += zk * wv.w;
            }
            hout[row * 8 + s] = o;
        } else {
            float o = z.x * w3.x + z.y * w3.y + z.z * w3.z + z.w * w3.w;
            o += __shfl_down_sync(FULLMASK, o, 4);
            o += __shfl_down_sync(FULLMASK, o, 2);
            o += __shfl_down_sync(FULLMASK, o, 1);
            if (s == 0) g_h3[row] = o;
        }
    }
}

// ---------------- 1-dim aggregate for last hop -----------------------------
__global__ void k_agg1d(const float* __restrict__ bias) {
    int i = blockIdx.x * blockDim.x + threadIdx.x;
    if (i >= NN) return;
    int b = g_row[i], e = g_row[i + 1];
    float z = g_h3[i];
    int p = b;
    for (; p + 4 <= e; p += 4) {
        float a0 = g_h3[g_edge[p].x];
        float a1 = g_h3[g_edge[p + 1].x];
        float a2 = g_h3[g_edge[p + 2].x];
        float a3 = g_h3[g_edge[p + 3].x];
        z += (a0 + a1) + (a2 + a3);
    }
    for (; p < e; p++) z += g_h3[g_edge[p].x];
    g_hop4[i] = tanhf((z + bias[0]) / (float)(e - b + 1));
}

// ---------------- per-graph: sort-pool + conv1 + pool + conv2 + dense ------
__global__ void k_final(const float* __restrict__ w1, const float* __restrict__ b1,
                        const float* __restrict__ w2, const float* __restrict__ b2,
                        const float* __restrict__ wo, const float* __restrict__ bo,
                        float* __restrict__ out) {
    __shared__ unsigned long long sk[1024];
    __shared__ float sfeat[30 * 97];
    __shared__ float sw1[16 * 97];
    __shared__ float sc1[16 * 30];
    __shared__ float sp2[16 * 15];
    __shared__ float sw2[32 * 16 * 5];
    __shared__ float sc2[352];

    int t = threadIdx.x, g = blockIdx.x;
    {
        float v = g_hop4[g * NPG + t];
        unsigned u = __float_as_uint(v);
        // ascending-sortable mapping, then invert for descending order
        unsigned asc = (u & 0x80000000u) ? ~u : (u | 0x80000000u);
        unsigned desc = ~asc;
        sk[t] = ((unsigned long long)desc << 32) | (unsigned)t;
    }
    __syncthreads();

    // bitonic sort ascending on packed keys == value desc, index asc on ties
    for (int k = 2; k <= 1024; k <<= 1) {
        for (int j = k >> 1; j > 0; j >>= 1) {
            int ixj = t ^ j;
            if (ixj > t) {
                unsigned long long A = sk[t], B = sk[ixj];
                bool ascdir = ((t & k) == 0);
                if ((A > B) == ascdir) { sk[t] = B; sk[ixj] = A; }
            }
            __syncthreads();
        }
    }

    const float* h1 = reinterpret_cast<const float*>(g_hop1);
    const float* h2 = reinterpret_cast<const float*>(g_hop2);
    const float* h3 = reinterpret_cast<const float*>(g_hop3);

    // stage weights + gather top-30 feature rows
    for (int i = t; i < 16 * 97; i += 1024) sw1[i] = w1[i];
    for (int i = t; i < 32 * 16 * 5; i += 1024) sw2[i] = w2[i];
    for (int i = t; i < 30 * 97; i += 1024) {
        int kk = i / 97, d = i % 97;
        int n = g * NPG + (int)(sk[kk] & 0xFFFFFFFFu);
        float f;
        if (d < 32)      f = h1[n * 32 + d];
        else if (d < 64) f = h2[n * 32 + (d - 32)];
        else if (d < 96) f = h3[n * 32 + (d - 64)];
        else             f = g_hop4[n];
        sfeat[i] = f;
    }
    __syncthreads();

    // conv1: 1->16 channels, kernel 97, stride 97 -> [16, 30], relu
    if (t < 480) {
        int c1 = t / 30, kk = t % 30;
        float acc = b1[c1];
        for (int d = 0; d < 97; d++) acc += sw1[c1 * 97 + d] * sfeat[kk * 97 + d];
        sc1[c1 * 30 + kk] = fmaxf(acc, 0.f);
    }
    __syncthreads();

    // maxpool(2,2) -> [16, 15]
    if (t < 240) {
        int c1 = t / 15, j = t % 15;
        sp2[c1 * 15 + j] = fmaxf(sc1[c1 * 30 + 2 * j], sc1[c1 * 30 + 2 * j + 1]);
    }
    __syncthreads();

    // conv2: 16->32 channels, kernel 5 -> [32, 11], relu
    if (t < 352) {
        int c2 = t / 11, tt = t % 11;
        float acc = b2[c2];
        for (int c1 = 0; c1 < 16; c1++) {
#pragma unroll
            for (int kk = 0; kk < 5; kk++)
                acc += sw2[(c2 * 16 + c1) * 5 + kk] * sp2[c1 * 15 + tt + kk];
        }
        sc2[c2 * 11 + tt] = fmaxf(acc, 0.f);
    }
    __syncthreads();

    // dense [352] @ [352,2] + relu
    if (t < 2) {
        float acc = bo[t];
        for (int f = 0; f < 352; f++) acc += sc2[f] * wo[f * 2 + t];
        out[g * 2 + t] = fmaxf(acc, 0.f);
    }
}

// ---------------- launch ----------------------------------------------------
extern "C" void kernel_launch(void* const* d_in, const int* in_sizes, int n_in,
                              void* d_out, int out_size) {
    (void)in_sizes; (void)n_in; (void)out_size;
    const float* node_feat = (const float*)d_in[0];
    const float* edge_feat = (const float*)d_in[1];
    const int*   ei        = (const int*)d_in[2];
    const float* W0 = (const float*)d_in[3];  const float* b0 = (const float*)d_in[4];
    const float* W1 = (const float*)d_in[5];  const float* b1 = (const float*)d_in[6];
    const float* W2 = (const float*)d_in[7];  const float* b2 = (const float*)d_in[8];
    const float* W3 = (const float*)d_in[9];  const float* b3 = (const float*)d_in[10];
    const float* wc1 = (const float*)d_in[11]; const float* bc1 = (const float*)d_in[12];
    const float* wc2 = (const float*)d_in[13]; const float* bc2 = (const float*)d_in[14];
    const float* wo  = (const float*)d_in[15]; const float* bo  = (const float*)d_in[16];
    float* out = (float*)d_out;

    k_zero<<<NN / 256, 256>>>();
    k_hist<<<EE / 2048, 256>>>(ei);
    k_scanA<<<128, 256>>>();
    k_scanB<<<1, 128>>>();
    k_scanC<<<128, 256>>>();
    k_fill<<<EE / 1024, 256>>>(ei);
    k_gemm0<<<NN / 128, 256>>>(node_feat, edge_feat, W0);
    k_agg<0><<<NN / 128, 256>>>(b0, W1);
    k_agg<1><<<NN / 128, 256>>>(b1, W2);
    k_agg<2><<<NN / 128, 256>>>(b2, W3);
    k_agg1d<<<NN / 256, 256>>>(b3);
    k_final<<<BGRAPH, 1024>>>(wc1, bc1, wc2, bc2, wo, bo, out);
}